// round 14
// baseline (speedup 1.0000x reference)
#include <cuda_runtime.h>
#include <cuda_fp16.h>
#include <cstdint>
#include <math.h>

#define DIM    1024
#define HEADS  16
#define DH     64
#define BATCH  2
#define QL     1024
#define KL     4096
#define INNER  4096
#define MQ     (BATCH*QL)
#define MKV    (BATCH*KL)

// 0.125 * log2(e): folded into Q projection so softmax works in exp2 domain
#define SCALEC 0.18033688011112042f

// ---------------- scratch ----------------
#define ALN __align__(256)
__device__ ALN __half w_q [DIM*DIM];
__device__ ALN __half w_kv[2*DIM*DIM];
__device__ ALN __half w_o [DIM*DIM];
__device__ ALN __half w_1 [INNER*DIM];
__device__ ALN __half w_2 [DIM*INNER];
__device__ ALN __half g_qln [MQ*DIM];
__device__ ALN __half g_kvpe[MKV*DIM];
__device__ ALN __half g_qp  [MQ*DIM];                           // x SCALEC
__device__ ALN __half g_kvp [MKV*2*DIM];                        // K|V
__device__ ALN __half g_ctx [MQ*DIM];
__device__ ALN float  g_attn[MQ*DIM];
__device__ ALN __half g_hb  [MQ*DIM];
__device__ ALN __half g_in  [MQ*INNER];

// ---------------- PTX helpers (sm_80-compatible only) ----------------
__device__ __forceinline__ uint32_t smem_u32(const void* p){ uint32_t a;
  asm("{ .reg .u64 t; cvta.to.shared.u64 t, %1; cvt.u32.u64 %0, t; }":"=r"(a):"l"(p)); return a; }
__device__ __forceinline__ void cp16(uint32_t d, const void* s){
  asm volatile("cp.async.cg.shared.global [%0],[%1],16;"::"r"(d),"l"(s)); }
#define CP_COMMIT() asm volatile("cp.async.commit_group;":::"memory")
#define CP_WAIT0()  asm volatile("cp.async.wait_group 0;":::"memory")
#define CP_WAIT1()  asm volatile("cp.async.wait_group 1;":::"memory")

__device__ __forceinline__ void ldsm4(uint32_t* r, uint32_t a){
  asm volatile("ldmatrix.sync.aligned.m8n8.x4.shared.b16 {%0,%1,%2,%3},[%4];"
    :"=r"(r[0]),"=r"(r[1]),"=r"(r[2]),"=r"(r[3]):"r"(a));
}
__device__ __forceinline__ void ldsm4t(uint32_t* r, uint32_t a){
  asm volatile("ldmatrix.sync.aligned.m8n8.x4.trans.shared.b16 {%0,%1,%2,%3},[%4];"
    :"=r"(r[0]),"=r"(r[1]),"=r"(r[2]),"=r"(r[3]):"r"(a));
}
// fp16 MMA, fp32 accumulate
__device__ __forceinline__ void mmah(float* d, const uint32_t* a, uint32_t b0, uint32_t b1){
  asm volatile("mma.sync.aligned.m16n8k16.row.col.f32.f16.f16.f32 "
    "{%0,%1,%2,%3},{%4,%5,%6,%7},{%8,%9},{%0,%1,%2,%3};"
    :"+f"(d[0]),"+f"(d[1]),"+f"(d[2]),"+f"(d[3])
    :"r"(a[0]),"r"(a[1]),"r"(a[2]),"r"(a[3]),"r"(b0),"r"(b1));
}
__device__ __forceinline__ uint32_t packh(float a, float b){
  __half2 h=__floats2half2_rn(a,b);
  return *(uint32_t*)&h;
}
__device__ __forceinline__ float ex2(float x){
  float r; asm("ex2.approx.ftz.f32 %0,%1;":"=f"(r):"f"(x)); return r;
}
// gelu(x) = x * (1 - 1/(exp(2z)+1)), z = 0.79788456(x + 0.044715 x^3)
__device__ __forceinline__ float gelu_fast(float x){
  const float z = 0.7978845608028654f*(x + 0.044715f*x*x*x);
  const float e = ex2(z*2.8853900817779268f);   // exp(2z)
  float r; asm("rcp.approx.ftz.f32 %0,%1;":"=f"(r):"f"(e+1.0f));
  return x - x*r;
}
__device__ __forceinline__ uint32_t soff(uint32_t r, uint32_t ch){
  return r*128u + ((ch ^ (r & 7u)) << 4);
}

// ---------------- elementwise ----------------
__global__ void __launch_bounds__(256) ln_half_kernel(const float* __restrict__ x,
    const float* __restrict__ sc_, const float* __restrict__ bi_,
    __half* __restrict__ oh){
  const int row=blockIdx.x, t=threadIdx.x;
  const float4 v=((const float4*)(x+(size_t)row*DIM))[t];
  float s=v.x+v.y+v.z+v.w, ss=v.x*v.x+v.y*v.y+v.z*v.z+v.w*v.w;
  #pragma unroll
  for(int o=16;o;o>>=1){ s+=__shfl_xor_sync(~0u,s,o); ss+=__shfl_xor_sync(~0u,ss,o); }
  __shared__ float sm1[8], sm2[8];
  if((t&31)==0){ sm1[t>>5]=s; sm2[t>>5]=ss; }
  __syncthreads();
  float tot=0.f,tot2=0.f;
  #pragma unroll
  for(int i=0;i<8;i++){ tot+=sm1[i]; tot2+=sm2[i]; }
  const float mean=tot*(1.f/DIM), var=tot2*(1.f/DIM)-mean*mean, inv=rsqrtf(var+1e-6f);
  const float4 sc=((const float4*)sc_)[t], bi=((const float4*)bi_)[t];
  float o0=(v.x-mean)*inv*sc.x+bi.x, o1=(v.y-mean)*inv*sc.y+bi.y;
  float o2=(v.z-mean)*inv*sc.z+bi.z, o3=(v.w-mean)*inv*sc.w+bi.w;
  ((uint2*)(oh+(size_t)row*DIM))[t]=make_uint2(packh(o0,o1),packh(o2,o3));
}

__global__ void __launch_bounds__(256) kvpe_half_kernel(const float* __restrict__ kv,
    const float* __restrict__ pe, const int* __restrict__ ids,
    __half* __restrict__ oh){
  const int row=blockIdx.x, t=threadIdx.x;
  const int id=ids[row];
  float4 a=((const float4*)(kv+(size_t)row*DIM))[t];
  const float4 p=((const float4*)(pe+(size_t)id*DIM))[t];
  a.x+=p.x; a.y+=p.y; a.z+=p.z; a.w+=p.w;
  ((uint2*)(oh+(size_t)row*DIM))[t]=make_uint2(packh(a.x,a.y),packh(a.z,a.w));
}

// W[K,N] -> Wt[N,K] single fp16, 64x64 tiles, vectorized
__global__ void __launch_bounds__(256) tconv_kernel(const float* __restrict__ W,
    __half* __restrict__ T, int K, int N){
  __shared__ float t[64][65];
  const int tid=threadIdx.x;
  const int bx=blockIdx.x*64, by=blockIdx.y*64;   // bx: N offset, by: K offset
  const int lr=tid>>4, lc=(tid&15)*4;
  #pragma unroll
  for(int i=0;i<4;i++){
    const int row=lr+i*16;
    const float4 v=*(const float4*)(W+(size_t)(by+row)*N+bx+lc);
    t[row][lc]=v.x; t[row][lc+1]=v.y; t[row][lc+2]=v.z; t[row][lc+3]=v.w;
  }
  __syncthreads();
  #pragma unroll
  for(int i=0;i<4;i++){
    const int n=lr+i*16;
    const uint32_t p0=packh(t[lc][n],   t[lc+1][n]);
    const uint32_t p1=packh(t[lc+2][n], t[lc+3][n]);
    *(uint2*)(T+(size_t)(bx+n)*K+by+lc)=make_uint2(p0,p1);
  }
}

// ---------------- fp16 1-pass GEMM: C = A[M,K] @ Wt[N,K]^T ----------------
// tile 128x128x64, 3-stage pipeline / single barrier, 2 CTAs/SM
// stage (32KB): A@0 (16KB), B@16384
#define MM1_STAGE 32768
#define MM1_SMEM  (3*MM1_STAGE)

__device__ __forceinline__ void mm1_load(const __half* A,const __half* B,
    uint32_t sb,int tid,int row0,int col0,int K,int s){
  const int k0=s*64; const uint32_t st=sb+(s%3)*MM1_STAGE;
  #pragma unroll
  for(int i=0;i<4;i++){
    int id=tid+256*i; uint32_t r=id>>3, c=id&7; uint32_t so=soff(r,c);
    cp16(st+so,       A+(size_t)(row0+r)*K+k0+c*8);
    cp16(st+16384+so, B+(size_t)(col0+r)*K+k0+c*8);
  }
}

// EPI: 0 = gelu -> fp16, 1 = +residual -> fp32, 2 = xSCALEC -> fp16, 4 = plain fp16
template <int EPI>
__global__ void __launch_bounds__(256,2) mm1_kernel(const __half* __restrict__ A,
    const __half* __restrict__ B,
    const float* __restrict__ R, float* __restrict__ Cf,
    __half* __restrict__ Ch, int N, int K){
  extern __shared__ char smc[];
  const uint32_t sb=smem_u32(smc);
  const int tid=threadIdx.x, wid=tid>>5, lane=tid&31;
  const int row0=blockIdx.y*128, col0=blockIdx.x*128;
  const int m0=(wid>>2)*64, n0=(wid&3)*32;

  float acc[4][4][4];
  #pragma unroll
  for(int i=0;i<4;i++)
    #pragma unroll
    for(int j=0;j<4;j++)
      #pragma unroll
      for(int k=0;k<4;k++) acc[i][j][k]=0.f;

  const int S=K/64;
  mm1_load(A,B,sb,tid,row0,col0,K,0); CP_COMMIT();
  mm1_load(A,B,sb,tid,row0,col0,K,1); CP_COMMIT();

  for(int s=0;s<S;s++){
    CP_WAIT1();
    __syncthreads();   // all warps done with stage s-1 -> slot (s+2)%3 free
    if(s+2<S) mm1_load(A,B,sb,tid,row0,col0,K,s+2);
    CP_COMMIT();
    const uint32_t st=sb+(s%3)*MM1_STAGE;
    #pragma unroll
    for(int kk=0;kk<4;kk++){
      const uint32_t chk=kk*2+(lane>>4);
      uint32_t bh[2][4];
      #pragma unroll
      for(int ni=0;ni<2;ni++){
        const uint32_t r=n0+ni*16+(lane&15);
        ldsm4(bh[ni], st+16384+soff(r,chk));
      }
      #pragma unroll
      for(int mi=0;mi<4;mi++){
        const uint32_t r=m0+mi*16+(lane&15);
        uint32_t a[4];
        ldsm4(a, st+soff(r,chk));
        #pragma unroll
        for(int nj=0;nj<4;nj++)
          mmah(acc[mi][nj], a, bh[nj>>1][nj&1], bh[nj>>1][(nj&1)+2]);
      }
    }
  }

  #pragma unroll
  for(int mi=0;mi<4;mi++){
    #pragma unroll
    for(int h=0;h<2;h++){
      const int grow=row0+m0+mi*16+(lane>>2)+h*8;
      #pragma unroll
      for(int nj=0;nj<4;nj++){
        const int gcol=col0+n0+nj*8+2*(lane&3);
        const float v0=acc[mi][nj][2*h], v1=acc[mi][nj][2*h+1];
        if(EPI==1){
          float2 rv=*(const float2*)(R+(size_t)grow*N+gcol);
          *(float2*)(Cf+(size_t)grow*N+gcol)=make_float2(v0+rv.x, v1+rv.y);
        } else if(EPI==0){
          *(uint32_t*)(Ch+(size_t)grow*N+gcol)=packh(gelu_fast(v0),gelu_fast(v1));
        } else if(EPI==2){
          *(uint32_t*)(Ch+(size_t)grow*N+gcol)=packh(v0*SCALEC,v1*SCALEC);
        } else {
          *(uint32_t*)(Ch+(size_t)grow*N+gcol)=packh(v0,v1);
        }
      }
    }
  }
}

// ---------------- FA2 attention (fp16 1-pass HMMA), 128 threads, 2 CTAs/SM ----------------
// smem: Q @0 (16KB); 3 stages @16384+slot*16384: K@+0 (8KB), V@+8192 (8KB). total 64KB
#define AT_SMEM 65536

__device__ __forceinline__ void attn_loadkv(const __half* KV,
    uint32_t sb,int tid,size_t kr0,int h,int slot){
  const uint32_t st=sb+16384+slot*16384;
  #pragma unroll
  for(int i=0;i<4;i++){
    int id=tid+128*i; uint32_t r=id>>3, c=id&7; uint32_t so=soff(r,c);
    const size_t g=(kr0+r)*2048 + (size_t)h*64 + c*8;
    cp16(st+so,      KV+g);
    cp16(st+8192+so, KV+g+1024);
  }
}

__global__ void __launch_bounds__(128,2) attn_kernel(const __half* __restrict__ Q,
    const __half* __restrict__ KV, __half* __restrict__ C){
  extern __shared__ char smc[];
  const uint32_t sb=smem_u32(smc);
  const int tid=threadIdx.x, wid=tid>>5, lane=tid&31;
  const int qt=blockIdx.x, h=blockIdx.y, b=blockIdx.z;
  const size_t qrow0=(size_t)(b*QL+qt*128);

  #pragma unroll
  for(int i=0;i<8;i++){
    int id=tid+128*i; uint32_t r=id>>3, c=id&7; uint32_t so=soff(r,c);
    cp16(sb+so, Q+(qrow0+r)*DIM + (size_t)h*64 + c*8);
  }
  attn_loadkv(KV,sb,tid,(size_t)b*KL,h,0); CP_COMMIT();
  attn_loadkv(KV,sb,tid,(size_t)b*KL+64,h,1); CP_COMMIT();

  float O[2][8][4];
  #pragma unroll
  for(int i=0;i<2;i++)
    #pragma unroll
    for(int j=0;j<8;j++)
      #pragma unroll
      for(int k=0;k<4;k++) O[i][j][k]=0.f;
  float mrun[2][2]={{-1e30f,-1e30f},{-1e30f,-1e30f}};
  float lrun[2][2]={{0.f,0.f},{0.f,0.f}};

  const int NT=KL/64;
  for(int t=0;t<NT;t++){
    CP_WAIT1();
    __syncthreads();   // all warps done with stage t-1 -> slot (t+2)%3 free
    if(t+2<NT) attn_loadkv(KV,sb,tid,(size_t)b*KL+(size_t)(t+2)*64,h,(t+2)%3);
    CP_COMMIT();
    const uint32_t st=sb+16384+(t%3)*16384;

    float S[2][8][4];
    #pragma unroll
    for(int i=0;i<2;i++)
      #pragma unroll
      for(int j=0;j<8;j++)
        #pragma unroll
        for(int k=0;k<4;k++) S[i][j][k]=0.f;
    #pragma unroll
    for(int kk=0;kk<4;kk++){
      const uint32_t chk=kk*2+(lane>>4);
      uint32_t q[2][4];
      #pragma unroll
      for(int mi=0;mi<2;mi++){
        const uint32_t r=wid*32+mi*16+(lane&15);
        ldsm4(q[mi], sb+soff(r,chk));
      }
      #pragma unroll
      for(int nk=0;nk<4;nk++){
        const uint32_t r=nk*16+(lane&15);
        uint32_t kh[4];
        ldsm4(kh, st+soff(r,chk));
        #pragma unroll
        for(int mi=0;mi<2;mi++){
          mmah(S[mi][2*nk],   q[mi], kh[0], kh[2]);
          mmah(S[mi][2*nk+1], q[mi], kh[1], kh[3]);
        }
      }
    }

    float alpha[2][2];
    #pragma unroll
    for(int mi=0;mi<2;mi++)
      #pragma unroll
      for(int hh=0;hh<2;hh++){
        float mx=-1e30f;
        #pragma unroll
        for(int nj=0;nj<8;nj++){ mx=fmaxf(mx,S[mi][nj][2*hh]); mx=fmaxf(mx,S[mi][nj][2*hh+1]); }
        mx=fmaxf(mx,__shfl_xor_sync(~0u,mx,1));
        mx=fmaxf(mx,__shfl_xor_sync(~0u,mx,2));
        const float mn=fmaxf(mrun[mi][hh],mx);
        alpha[mi][hh]=ex2(mrun[mi][hh]-mn);
        mrun[mi][hh]=mn;
        float sum=0.f;
        #pragma unroll
        for(int nj=0;nj<8;nj++){
          float e0=ex2(S[mi][nj][2*hh]-mn), e1=ex2(S[mi][nj][2*hh+1]-mn);
          S[mi][nj][2*hh]=e0; S[mi][nj][2*hh+1]=e1; sum+=e0+e1;
        }
        sum+=__shfl_xor_sync(~0u,sum,1);
        sum+=__shfl_xor_sync(~0u,sum,2);
        lrun[mi][hh]=lrun[mi][hh]*alpha[mi][hh]+sum;
        #pragma unroll
        for(int nj=0;nj<8;nj++){
          O[mi][nj][2*hh]  *=alpha[mi][hh];
          O[mi][nj][2*hh+1]*=alpha[mi][hh];
        }
      }

    #pragma unroll
    for(int ki=0;ki<4;ki++){
      uint32_t p[2][4];
      #pragma unroll
      for(int mi=0;mi<2;mi++){
        p[mi][0]=packh(S[mi][2*ki][0],  S[mi][2*ki][1]);
        p[mi][1]=packh(S[mi][2*ki][2],  S[mi][2*ki][3]);
        p[mi][2]=packh(S[mi][2*ki+1][0],S[mi][2*ki+1][1]);
        p[mi][3]=packh(S[mi][2*ki+1][2],S[mi][2*ki+1][3]);
      }
      #pragma unroll
      for(int nd=0;nd<4;nd++){
        const uint32_t r=ki*16+(lane&15);
        const uint32_t chk=nd*2+(lane>>4);
        uint32_t vh[4];
        ldsm4t(vh, st+8192+soff(r,chk));
        #pragma unroll
        for(int mi=0;mi<2;mi++){
          mmah(O[mi][2*nd],   p[mi], vh[0], vh[1]);
          mmah(O[mi][2*nd+1], p[mi], vh[2], vh[3]);
        }
      }
    }
  }

  #pragma unroll
  for(int mi=0;mi<2;mi++)
    #pragma unroll
    for(int hh=0;hh<2;hh++){
      const float inv=1.f/lrun[mi][hh];
      const size_t grow=qrow0+wid*32+mi*16+(lane>>2)+hh*8;
      #pragma unroll
      for(int nj=0;nj<8;nj++){
        const int gcol=h*64+nj*8+2*(lane&3);
        *(uint32_t*)(C+grow*DIM+gcol)=packh(O[mi][nj][2*hh]*inv, O[mi][nj][2*hh+1]*inv);
      }
    }
}

// ---------------- launch ----------------
extern "C" void kernel_launch(void* const* d_in, const int* in_sizes, int n_in,
                              void* d_out, int out_size){
  const float* q   =(const float*)d_in[0];
  const float* kv  =(const float*)d_in[1];
  const int*   ids =(const int*)  d_in[3];
  const float* ln1s=(const float*)d_in[4];
  const float* ln1b=(const float*)d_in[5];
  const float* Wq  =(const float*)d_in[6];
  const float* Wkv =(const float*)d_in[7];
  const float* Wo  =(const float*)d_in[8];
  const float* ln2s=(const float*)d_in[9];
  const float* ln2b=(const float*)d_in[10];
  const float* W1  =(const float*)d_in[11];
  const float* W2  =(const float*)d_in[12];
  const float* pe  =(const float*)d_in[13];
  float* out=(float*)d_out;

#define SYM(v,s) void* v##_; cudaGetSymbolAddress(&v##_,s);
  SYM(wq,w_q) SYM(wkv,w_kv) SYM(wo,w_o) SYM(w1,w_1) SYM(w2,w_2)
  SYM(qln,g_qln) SYM(kpe,g_kvpe) SYM(qp,g_qp) SYM(kvp,g_kvp)
  SYM(ctx,g_ctx) SYM(atf,g_attn) SYM(hbuf,g_hb) SYM(inbuf,g_in)
#undef SYM
#define HF(p) ((__half*)p##_)
#define FL(p) ((float*)p##_)

  cudaFuncSetAttribute(mm1_kernel<0>, cudaFuncAttributeMaxDynamicSharedMemorySize, MM1_SMEM);
  cudaFuncSetAttribute(mm1_kernel<1>, cudaFuncAttributeMaxDynamicSharedMemorySize, MM1_SMEM);
  cudaFuncSetAttribute(mm1_kernel<2>, cudaFuncAttributeMaxDynamicSharedMemorySize, MM1_SMEM);
  cudaFuncSetAttribute(mm1_kernel<4>, cudaFuncAttributeMaxDynamicSharedMemorySize, MM1_SMEM);
  cudaFuncSetAttribute(attn_kernel,   cudaFuncAttributeMaxDynamicSharedMemorySize, AT_SMEM);

  // ncu captures launch #4 -> keep the biggest GEMM (kv-proj) there
  tconv_kernel<<<dim3(2*DIM/64,DIM/64),256>>>(Wkv, HF(wkv), DIM, 2*DIM);             // 1
  kvpe_half_kernel<<<MKV,256>>>(kv, pe, ids, HF(kpe));                               // 2
  tconv_kernel<<<dim3(DIM/64,DIM/64),256>>>(Wq, HF(wq), DIM, DIM);                   // 3
  mm1_kernel<4><<<dim3(2*DIM/128,MKV/128),256,MM1_SMEM>>>(HF(kpe),HF(wkv),
      nullptr,nullptr,HF(kvp),2*DIM,DIM);                                            // 4 (ncu)
  ln_half_kernel<<<MQ,256>>>(q, ln1s, ln1b, HF(qln));                                // 5
  mm1_kernel<2><<<dim3(DIM/128,MQ/128),256,MM1_SMEM>>>(HF(qln),HF(wq),
      nullptr,nullptr,HF(qp),DIM,DIM);                                               // 6
  tconv_kernel<<<dim3(DIM/64,DIM/64),256>>>(Wo, HF(wo), DIM, DIM);                   // 7
  tconv_kernel<<<dim3(INNER/64,DIM/64),256>>>(W1, HF(w1), DIM, INNER);               // 8
  tconv_kernel<<<dim3(DIM/64,INNER/64),256>>>(W2, HF(w2), INNER, DIM);               // 9

  attn_kernel<<<dim3(QL/128,HEADS,BATCH),128,AT_SMEM>>>(HF(qp),HF(kvp),HF(ctx));     // 10

  mm1_kernel<1><<<dim3(DIM/128,MQ/128),256,MM1_SMEM>>>(HF(ctx),HF(wo),
      q,FL(atf),nullptr,DIM,DIM);                                                    // 11
  ln_half_kernel<<<MQ,256>>>(FL(atf), ln2s, ln2b, HF(hbuf));                         // 12
  mm1_kernel<0><<<dim3(INNER/128,MQ/128),256,MM1_SMEM>>>(HF(hbuf),HF(w1),
      nullptr,nullptr,HF(inbuf),INNER,DIM);                                          // 13
  mm1_kernel<1><<<dim3(DIM/128,MQ/128),256,MM1_SMEM>>>(HF(inbuf),HF(w2),
      FL(atf),out,nullptr,DIM,INNER);                                                // 14
}

// round 15
// speedup vs baseline: 1.0605x; 1.0605x over previous
#include <cuda_runtime.h>
#include <cuda_fp16.h>
#include <cstdint>
#include <math.h>

#define DIM    1024
#define HEADS  16
#define DH     64
#define BATCH  2
#define QL     1024
#define KL     4096
#define INNER  4096
#define MQ     (BATCH*QL)
#define MKV    (BATCH*KL)

// 0.125 * log2(e): folded into Q projection so softmax works in exp2 domain
#define SCALEC 0.18033688011112042f

// ---------------- scratch ----------------
#define ALN __align__(256)
__device__ ALN __half w_q [DIM*DIM];
__device__ ALN __half w_kv[2*DIM*DIM];
__device__ ALN __half w_o [DIM*DIM];
__device__ ALN __half w_1 [INNER*DIM];
__device__ ALN __half w_2 [DIM*INNER];
__device__ ALN __half g_qln [MQ*DIM];
__device__ ALN __half g_kvpe[MKV*DIM];
__device__ ALN __half g_qp  [MQ*DIM];                           // x SCALEC
__device__ ALN __half g_kvp [MKV*2*DIM];                        // K|V
__device__ ALN __half g_ctx [MQ*DIM];
__device__ ALN float  g_attn[MQ*DIM];
__device__ ALN __half g_hb  [MQ*DIM];
__device__ ALN __half g_in  [MQ*INNER];

// ---------------- PTX helpers (sm_80-compatible only) ----------------
__device__ __forceinline__ uint32_t smem_u32(const void* p){ uint32_t a;
  asm("{ .reg .u64 t; cvta.to.shared.u64 t, %1; cvt.u32.u64 %0, t; }":"=r"(a):"l"(p)); return a; }
__device__ __forceinline__ void cp16(uint32_t d, const void* s){
  asm volatile("cp.async.cg.shared.global [%0],[%1],16;"::"r"(d),"l"(s)); }
#define CP_COMMIT() asm volatile("cp.async.commit_group;":::"memory")
#define CP_WAIT0()  asm volatile("cp.async.wait_group 0;":::"memory")
#define CP_WAIT1()  asm volatile("cp.async.wait_group 1;":::"memory")
#define CP_WAIT2()  asm volatile("cp.async.wait_group 2;":::"memory")

__device__ __forceinline__ void ldsm4(uint32_t* r, uint32_t a){
  asm volatile("ldmatrix.sync.aligned.m8n8.x4.shared.b16 {%0,%1,%2,%3},[%4];"
    :"=r"(r[0]),"=r"(r[1]),"=r"(r[2]),"=r"(r[3]):"r"(a));
}
__device__ __forceinline__ void ldsm4t(uint32_t* r, uint32_t a){
  asm volatile("ldmatrix.sync.aligned.m8n8.x4.trans.shared.b16 {%0,%1,%2,%3},[%4];"
    :"=r"(r[0]),"=r"(r[1]),"=r"(r[2]),"=r"(r[3]):"r"(a));
}
// fp16 MMA, fp32 accumulate
__device__ __forceinline__ void mmah(float* d, const uint32_t* a, uint32_t b0, uint32_t b1){
  asm volatile("mma.sync.aligned.m16n8k16.row.col.f32.f16.f16.f32 "
    "{%0,%1,%2,%3},{%4,%5,%6,%7},{%8,%9},{%0,%1,%2,%3};"
    :"+f"(d[0]),"+f"(d[1]),"+f"(d[2]),"+f"(d[3])
    :"r"(a[0]),"r"(a[1]),"r"(a[2]),"r"(a[3]),"r"(b0),"r"(b1));
}
__device__ __forceinline__ uint32_t packh(float a, float b){
  __half2 h=__floats2half2_rn(a,b);
  return *(uint32_t*)&h;
}
__device__ __forceinline__ float ex2(float x){
  float r; asm("ex2.approx.ftz.f32 %0,%1;":"=f"(r):"f"(x)); return r;
}
// gelu(x) = x * (1 - 1/(exp(2z)+1)), z = 0.79788456(x + 0.044715 x^3)
__device__ __forceinline__ float gelu_fast(float x){
  const float z = 0.7978845608028654f*(x + 0.044715f*x*x*x);
  const float e = ex2(z*2.8853900817779268f);   // exp(2z)
  float r; asm("rcp.approx.ftz.f32 %0,%1;":"=f"(r):"f"(e+1.0f));
  return x - x*r;
}
__device__ __forceinline__ uint32_t soff(uint32_t r, uint32_t ch){
  return r*128u + ((ch ^ (r & 7u)) << 4);
}

// ---------------- elementwise ----------------
__global__ void __launch_bounds__(256) ln_half_kernel(const float* __restrict__ x,
    const float* __restrict__ sc_, const float* __restrict__ bi_,
    __half* __restrict__ oh){
  const int row=blockIdx.x, t=threadIdx.x;
  const float4 v=((const float4*)(x+(size_t)row*DIM))[t];
  float s=v.x+v.y+v.z+v.w, ss=v.x*v.x+v.y*v.y+v.z*v.z+v.w*v.w;
  #pragma unroll
  for(int o=16;o;o>>=1){ s+=__shfl_xor_sync(~0u,s,o); ss+=__shfl_xor_sync(~0u,ss,o); }
  __shared__ float sm1[8], sm2[8];
  if((t&31)==0){ sm1[t>>5]=s; sm2[t>>5]=ss; }
  __syncthreads();
  float tot=0.f,tot2=0.f;
  #pragma unroll
  for(int i=0;i<8;i++){ tot+=sm1[i]; tot2+=sm2[i]; }
  const float mean=tot*(1.f/DIM), var=tot2*(1.f/DIM)-mean*mean, inv=rsqrtf(var+1e-6f);
  const float4 sc=((const float4*)sc_)[t], bi=((const float4*)bi_)[t];
  float o0=(v.x-mean)*inv*sc.x+bi.x, o1=(v.y-mean)*inv*sc.y+bi.y;
  float o2=(v.z-mean)*inv*sc.z+bi.z, o3=(v.w-mean)*inv*sc.w+bi.w;
  ((uint2*)(oh+(size_t)row*DIM))[t]=make_uint2(packh(o0,o1),packh(o2,o3));
}

__global__ void __launch_bounds__(256) kvpe_half_kernel(const float* __restrict__ kv,
    const float* __restrict__ pe, const int* __restrict__ ids,
    __half* __restrict__ oh){
  const int row=blockIdx.x, t=threadIdx.x;
  const int id=ids[row];
  float4 a=((const float4*)(kv+(size_t)row*DIM))[t];
  const float4 p=((const float4*)(pe+(size_t)id*DIM))[t];
  a.x+=p.x; a.y+=p.y; a.z+=p.z; a.w+=p.w;
  ((uint2*)(oh+(size_t)row*DIM))[t]=make_uint2(packh(a.x,a.y),packh(a.z,a.w));
}

// W[K,N] -> Wt[N,K] single fp16, 64x64 tiles, vectorized
__global__ void __launch_bounds__(256) tconv_kernel(const float* __restrict__ W,
    __half* __restrict__ T, int K, int N){
  __shared__ float t[64][65];
  const int tid=threadIdx.x;
  const int bx=blockIdx.x*64, by=blockIdx.y*64;   // bx: N offset, by: K offset
  const int lr=tid>>4, lc=(tid&15)*4;
  #pragma unroll
  for(int i=0;i<4;i++){
    const int row=lr+i*16;
    const float4 v=*(const float4*)(W+(size_t)(by+row)*N+bx+lc);
    t[row][lc]=v.x; t[row][lc+1]=v.y; t[row][lc+2]=v.z; t[row][lc+3]=v.w;
  }
  __syncthreads();
  #pragma unroll
  for(int i=0;i<4;i++){
    const int n=lr+i*16;
    const uint32_t p0=packh(t[lc][n],   t[lc+1][n]);
    const uint32_t p1=packh(t[lc+2][n], t[lc+3][n]);
    *(uint2*)(T+(size_t)(bx+n)*K+by+lc)=make_uint2(p0,p1);
  }
}

// ---------------- fp16 1-pass GEMM: C = A[M,K] @ Wt[N,K]^T ----------------
// tile 128x128x64, 2-stage pipeline, 2 CTAs/SM; stage (32KB): A@0 (16KB), B@16384
#define MM1_STAGE 32768
#define MM1_SMEM  (2*MM1_STAGE)

__device__ __forceinline__ void mm1_load(const __half* A,const __half* B,
    uint32_t sb,int tid,int row0,int col0,int K,int s){
  const int k0=s*64; const uint32_t st=sb+(s&1)*MM1_STAGE;
  #pragma unroll
  for(int i=0;i<4;i++){
    int id=tid+256*i; uint32_t r=id>>3, c=id&7; uint32_t so=soff(r,c);
    cp16(st+so,       A+(size_t)(row0+r)*K+k0+c*8);
    cp16(st+16384+so, B+(size_t)(col0+r)*K+k0+c*8);
  }
}

// EPI: 0 = gelu -> fp16, 1 = +residual -> fp32, 2 = xSCALEC -> fp16, 4 = plain fp16
template <int EPI>
__global__ void __launch_bounds__(256,2) mm1_kernel(const __half* __restrict__ A,
    const __half* __restrict__ B,
    const float* __restrict__ R, float* __restrict__ Cf,
    __half* __restrict__ Ch, int N, int K){
  extern __shared__ char smc[];
  const uint32_t sb=smem_u32(smc);
  const int tid=threadIdx.x, wid=tid>>5, lane=tid&31;
  const int row0=blockIdx.y*128, col0=blockIdx.x*128;
  const int m0=(wid>>2)*64, n0=(wid&3)*32;

  float acc[4][4][4];
  #pragma unroll
  for(int i=0;i<4;i++)
    #pragma unroll
    for(int j=0;j<4;j++)
      #pragma unroll
      for(int k=0;k<4;k++) acc[i][j][k]=0.f;

  const int S=K/64;
  mm1_load(A,B,sb,tid,row0,col0,K,0); CP_COMMIT();
  mm1_load(A,B,sb,tid,row0,col0,K,1); CP_COMMIT();

  for(int s=0;s<S;s++){
    CP_WAIT1();
    __syncthreads();
    const uint32_t st=sb+(s&1)*MM1_STAGE;
    #pragma unroll
    for(int kk=0;kk<4;kk++){
      const uint32_t chk=kk*2+(lane>>4);
      uint32_t bh[2][4];
      #pragma unroll
      for(int ni=0;ni<2;ni++){
        const uint32_t r=n0+ni*16+(lane&15);
        ldsm4(bh[ni], st+16384+soff(r,chk));
      }
      #pragma unroll
      for(int mi=0;mi<4;mi++){
        const uint32_t r=m0+mi*16+(lane&15);
        uint32_t a[4];
        ldsm4(a, st+soff(r,chk));
        #pragma unroll
        for(int nj=0;nj<4;nj++)
          mmah(acc[mi][nj], a, bh[nj>>1][nj&1], bh[nj>>1][(nj&1)+2]);
      }
    }
    __syncthreads();
    if(s+2<S) mm1_load(A,B,sb,tid,row0,col0,K,s+2);
    CP_COMMIT();
  }

  #pragma unroll
  for(int mi=0;mi<4;mi++){
    #pragma unroll
    for(int h=0;h<2;h++){
      const int grow=row0+m0+mi*16+(lane>>2)+h*8;
      #pragma unroll
      for(int nj=0;nj<4;nj++){
        const int gcol=col0+n0+nj*8+2*(lane&3);
        const float v0=acc[mi][nj][2*h], v1=acc[mi][nj][2*h+1];
        if(EPI==1){
          float2 rv=*(const float2*)(R+(size_t)grow*N+gcol);
          *(float2*)(Cf+(size_t)grow*N+gcol)=make_float2(v0+rv.x, v1+rv.y);
        } else if(EPI==0){
          *(uint32_t*)(Ch+(size_t)grow*N+gcol)=packh(gelu_fast(v0),gelu_fast(v1));
        } else if(EPI==2){
          *(uint32_t*)(Ch+(size_t)grow*N+gcol)=packh(v0*SCALEC,v1*SCALEC);
        } else {
          *(uint32_t*)(Ch+(size_t)grow*N+gcol)=packh(v0,v1);
        }
      }
    }
  }
}

// ---------------- FA2 attention (fp16 1-pass HMMA), 128 threads, 2 CTAs/SM ----------------
// smem: Q @0 (16KB); stage buf @16384+buf*16384: K@+0 (8KB), V@+8192 (8KB). total 48KB
// Q fragments preloaded into registers once (reused across all 64 kv tiles).
#define AT_SMEM 49152

__device__ __forceinline__ void attn_loadkv(const __half* KV,
    uint32_t sb,int tid,size_t kr0,int h,int buf){
  const uint32_t st=sb+16384+buf*16384;
  #pragma unroll
  for(int i=0;i<4;i++){
    int id=tid+128*i; uint32_t r=id>>3, c=id&7; uint32_t so=soff(r,c);
    const size_t g=(kr0+r)*2048 + (size_t)h*64 + c*8;
    cp16(st+so,      KV+g);
    cp16(st+8192+so, KV+g+1024);
  }
}

__global__ void __launch_bounds__(128,2) attn_kernel(const __half* __restrict__ Q,
    const __half* __restrict__ KV, __half* __restrict__ C){
  extern __shared__ char smc[];
  const uint32_t sb=smem_u32(smc);
  const int tid=threadIdx.x, wid=tid>>5, lane=tid&31;
  const int qt=blockIdx.x, h=blockIdx.y, b=blockIdx.z;
  const size_t qrow0=(size_t)(b*QL+qt*128);

  #pragma unroll
  for(int i=0;i<8;i++){
    int id=tid+128*i; uint32_t r=id>>3, c=id&7; uint32_t so=soff(r,c);
    cp16(sb+so, Q+(qrow0+r)*DIM + (size_t)h*64 + c*8);
  }
  CP_COMMIT();
  attn_loadkv(KV,sb,tid,(size_t)b*KL,h,0); CP_COMMIT();
  attn_loadkv(KV,sb,tid,(size_t)b*KL+64,h,1); CP_COMMIT();

  // preload Q fragments into registers (Q reused for all kv tiles)
  uint32_t qreg[4][2][4];
  CP_WAIT2();          // Q group done (kv0, kv1 may be outstanding)
  __syncthreads();
  #pragma unroll
  for(int kk=0;kk<4;kk++){
    const uint32_t chk=kk*2+(lane>>4);
    #pragma unroll
    for(int mi=0;mi<2;mi++){
      const uint32_t r=wid*32+mi*16+(lane&15);
      ldsm4(qreg[kk][mi], sb+soff(r,chk));
    }
  }

  float O[2][8][4];
  #pragma unroll
  for(int i=0;i<2;i++)
    #pragma unroll
    for(int j=0;j<8;j++)
      #pragma unroll
      for(int k=0;k<4;k++) O[i][j][k]=0.f;
  float mrun[2][2]={{-1e30f,-1e30f},{-1e30f,-1e30f}};
  float lrun[2][2]={{0.f,0.f},{0.f,0.f}};

  const int NT=KL/64;
  for(int t=0;t<NT;t++){
    if(t+1<NT) CP_WAIT1(); else CP_WAIT0();
    __syncthreads();
    const uint32_t st=sb+16384+(t&1)*16384;

    float S[2][8][4];
    #pragma unroll
    for(int i=0;i<2;i++)
      #pragma unroll
      for(int j=0;j<8;j++)
        #pragma unroll
        for(int k=0;k<4;k++) S[i][j][k]=0.f;
    #pragma unroll
    for(int kk=0;kk<4;kk++){
      const uint32_t chk=kk*2+(lane>>4);
      #pragma unroll
      for(int nk=0;nk<4;nk++){
        const uint32_t r=nk*16+(lane&15);
        uint32_t kh[4];
        ldsm4(kh, st+soff(r,chk));
        #pragma unroll
        for(int mi=0;mi<2;mi++){
          mmah(S[mi][2*nk],   qreg[kk][mi], kh[0], kh[2]);
          mmah(S[mi][2*nk+1], qreg[kk][mi], kh[1], kh[3]);
        }
      }
    }

    float alpha[2][2];
    #pragma unroll
    for(int mi=0;mi<2;mi++)
      #pragma unroll
      for(int hh=0;hh<2;hh++){
        float mx=-1e30f;
        #pragma unroll
        for(int nj=0;nj<8;nj++){ mx=fmaxf(mx,S[mi][nj][2*hh]); mx=fmaxf(mx,S[mi][nj][2*hh+1]); }
        mx=fmaxf(mx,__shfl_xor_sync(~0u,mx,1));
        mx=fmaxf(mx,__shfl_xor_sync(~0u,mx,2));
        const float mn=fmaxf(mrun[mi][hh],mx);
        alpha[mi][hh]=ex2(mrun[mi][hh]-mn);
        mrun[mi][hh]=mn;
        float sum=0.f;
        #pragma unroll
        for(int nj=0;nj<8;nj++){
          float e0=ex2(S[mi][nj][2*hh]-mn), e1=ex2(S[mi][nj][2*hh+1]-mn);
          S[mi][nj][2*hh]=e0; S[mi][nj][2*hh+1]=e1; sum+=e0+e1;
        }
        sum+=__shfl_xor_sync(~0u,sum,1);
        sum+=__shfl_xor_sync(~0u,sum,2);
        lrun[mi][hh]=lrun[mi][hh]*alpha[mi][hh]+sum;
        #pragma unroll
        for(int nj=0;nj<8;nj++){
          O[mi][nj][2*hh]  *=alpha[mi][hh];
          O[mi][nj][2*hh+1]*=alpha[mi][hh];
        }
      }

    #pragma unroll
    for(int ki=0;ki<4;ki++){
      uint32_t p[2][4];
      #pragma unroll
      for(int mi=0;mi<2;mi++){
        p[mi][0]=packh(S[mi][2*ki][0],  S[mi][2*ki][1]);
        p[mi][1]=packh(S[mi][2*ki][2],  S[mi][2*ki][3]);
        p[mi][2]=packh(S[mi][2*ki+1][0],S[mi][2*ki+1][1]);
        p[mi][3]=packh(S[mi][2*ki+1][2],S[mi][2*ki+1][3]);
      }
      #pragma unroll
      for(int nd=0;nd<4;nd++){
        const uint32_t r=ki*16+(lane&15);
        const uint32_t chk=nd*2+(lane>>4);
        uint32_t vh[4];
        ldsm4t(vh, st+8192+soff(r,chk));
        #pragma unroll
        for(int mi=0;mi<2;mi++){
          mmah(O[mi][2*nd],   p[mi], vh[0], vh[1]);
          mmah(O[mi][2*nd+1], p[mi], vh[2], vh[3]);
        }
      }
    }
    __syncthreads();
    if(t+2<NT){ attn_loadkv(KV,sb,tid,(size_t)b*KL+(size_t)(t+2)*64,h,t&1); CP_COMMIT(); }
  }

  #pragma unroll
  for(int mi=0;mi<2;mi++)
    #pragma unroll
    for(int hh=0;hh<2;hh++){
      const float inv=1.f/lrun[mi][hh];
      const size_t grow=qrow0+wid*32+mi*16+(lane>>2)+hh*8;
      #pragma unroll
      for(int nj=0;nj<8;nj++){
        const int gcol=h*64+nj*8+2*(lane&3);
        *(uint32_t*)(C+grow*DIM+gcol)=packh(O[mi][nj][2*hh]*inv, O[mi][nj][2*hh+1]*inv);
      }
    }
}

// ---------------- launch ----------------
extern "C" void kernel_launch(void* const* d_in, const int* in_sizes, int n_in,
                              void* d_out, int out_size){
  const float* q   =(const float*)d_in[0];
  const float* kv  =(const float*)d_in[1];
  const int*   ids =(const int*)  d_in[3];
  const float* ln1s=(const float*)d_in[4];
  const float* ln1b=(const float*)d_in[5];
  const float* Wq  =(const float*)d_in[6];
  const float* Wkv =(const float*)d_in[7];
  const float* Wo  =(const float*)d_in[8];
  const float* ln2s=(const float*)d_in[9];
  const float* ln2b=(const float*)d_in[10];
  const float* W1  =(const float*)d_in[11];
  const float* W2  =(const float*)d_in[12];
  const float* pe  =(const float*)d_in[13];
  float* out=(float*)d_out;

#define SYM(v,s) void* v##_; cudaGetSymbolAddress(&v##_,s);
  SYM(wq,w_q) SYM(wkv,w_kv) SYM(wo,w_o) SYM(w1,w_1) SYM(w2,w_2)
  SYM(qln,g_qln) SYM(kpe,g_kvpe) SYM(qp,g_qp) SYM(kvp,g_kvp)
  SYM(ctx,g_ctx) SYM(atf,g_attn) SYM(hbuf,g_hb) SYM(inbuf,g_in)
#undef SYM
#define HF(p) ((__half*)p##_)
#define FL(p) ((float*)p##_)

  cudaFuncSetAttribute(mm1_kernel<0>, cudaFuncAttributeMaxDynamicSharedMemorySize, MM1_SMEM);
  cudaFuncSetAttribute(mm1_kernel<1>, cudaFuncAttributeMaxDynamicSharedMemorySize, MM1_SMEM);
  cudaFuncSetAttribute(mm1_kernel<2>, cudaFuncAttributeMaxDynamicSharedMemorySize, MM1_SMEM);
  cudaFuncSetAttribute(mm1_kernel<4>, cudaFuncAttributeMaxDynamicSharedMemorySize, MM1_SMEM);
  cudaFuncSetAttribute(attn_kernel,   cudaFuncAttributeMaxDynamicSharedMemorySize, AT_SMEM);

  // ncu captures launch #4 -> keep the biggest GEMM (kv-proj) there
  tconv_kernel<<<dim3(2*DIM/64,DIM/64),256>>>(Wkv, HF(wkv), DIM, 2*DIM);             // 1
  kvpe_half_kernel<<<MKV,256>>>(kv, pe, ids, HF(kpe));                               // 2
  tconv_kernel<<<dim3(DIM/64,DIM/64),256>>>(Wq, HF(wq), DIM, DIM);                   // 3
  mm1_kernel<4><<<dim3(2*DIM/128,MKV/128),256,MM1_SMEM>>>(HF(kpe),HF(wkv),
      nullptr,nullptr,HF(kvp),2*DIM,DIM);                                            // 4 (ncu)
  ln_half_kernel<<<MQ,256>>>(q, ln1s, ln1b, HF(qln));                                // 5
  mm1_kernel<2><<<dim3(DIM/128,MQ/128),256,MM1_SMEM>>>(HF(qln),HF(wq),
      nullptr,nullptr,HF(qp),DIM,DIM);                                               // 6
  tconv_kernel<<<dim3(DIM/64,DIM/64),256>>>(Wo, HF(wo), DIM, DIM);                   // 7
  tconv_kernel<<<dim3(INNER/64,DIM/64),256>>>(W1, HF(w1), DIM, INNER);               // 8
  tconv_kernel<<<dim3(DIM/64,INNER/64),256>>>(W2, HF(w2), INNER, DIM);               // 9

  attn_kernel<<<dim3(QL/128,HEADS,BATCH),128,AT_SMEM>>>(HF(qp),HF(kvp),HF(ctx));     // 10

  mm1_kernel<1><<<dim3(DIM/128,MQ/128),256,MM1_SMEM>>>(HF(ctx),HF(wo),
      q,FL(atf),nullptr,DIM,DIM);                                                    // 11
  ln_half_kernel<<<MQ,256>>>(FL(atf), ln2s, ln2b, HF(hbuf));                         // 12
  mm1_kernel<0><<<dim3(INNER/128,MQ/128),256,MM1_SMEM>>>(HF(hbuf),HF(w1),
      nullptr,nullptr,HF(inbuf),INNER,DIM);                                          // 13
  mm1_kernel<1><<<dim3(DIM/128,MQ/128),256,MM1_SMEM>>>(HF(inbuf),HF(w2),
      FL(atf),out,nullptr,DIM,INNER);                                                // 14
}

// round 16
// speedup vs baseline: 1.0642x; 1.0034x over previous
#include <cuda_runtime.h>
#include <cuda_fp16.h>
#include <cstdint>
#include <math.h>

#define DIM    1024
#define HEADS  16
#define DH     64
#define BATCH  2
#define QL     1024
#define KL     4096
#define INNER  4096
#define MQ     (BATCH*QL)
#define MKV    (BATCH*KL)

// 0.125 * log2(e): folded into Q projection so softmax works in exp2 domain
#define SCALEC 0.18033688011112042f

// ---------------- scratch ----------------
#define ALN __align__(256)
__device__ ALN __half w_q [DIM*DIM];
__device__ ALN __half w_kv[2*DIM*DIM];
__device__ ALN __half w_o [DIM*DIM];
__device__ ALN __half w_1 [INNER*DIM];
__device__ ALN __half w_2 [DIM*INNER];
__device__ ALN __half g_qln [MQ*DIM];
__device__ ALN __half g_kvpe[MKV*DIM];
__device__ ALN __half g_qp  [MQ*DIM];                           // x SCALEC
__device__ ALN __half g_kvp [MKV*2*DIM];                        // K|V
__device__ ALN __half g_ctx [MQ*DIM];
__device__ ALN float  g_attn[MQ*DIM];
__device__ ALN __half g_hb  [MQ*DIM];
__device__ ALN __half g_in  [MQ*INNER];

// ---------------- PTX helpers (sm_80-compatible only) ----------------
__device__ __forceinline__ uint32_t smem_u32(const void* p){ uint32_t a;
  asm("{ .reg .u64 t; cvta.to.shared.u64 t, %1; cvt.u32.u64 %0, t; }":"=r"(a):"l"(p)); return a; }
__device__ __forceinline__ void cp16(uint32_t d, const void* s){
  asm volatile("cp.async.cg.shared.global [%0],[%1],16;"::"r"(d),"l"(s)); }
#define CP_COMMIT() asm volatile("cp.async.commit_group;":::"memory")
#define CP_WAIT0()  asm volatile("cp.async.wait_group 0;":::"memory")
#define CP_WAIT1()  asm volatile("cp.async.wait_group 1;":::"memory")
#define CP_WAIT2()  asm volatile("cp.async.wait_group 2;":::"memory")

__device__ __forceinline__ void ldsm4(uint32_t* r, uint32_t a){
  asm volatile("ldmatrix.sync.aligned.m8n8.x4.shared.b16 {%0,%1,%2,%3},[%4];"
    :"=r"(r[0]),"=r"(r[1]),"=r"(r[2]),"=r"(r[3]):"r"(a));
}
__device__ __forceinline__ void ldsm4t(uint32_t* r, uint32_t a){
  asm volatile("ldmatrix.sync.aligned.m8n8.x4.trans.shared.b16 {%0,%1,%2,%3},[%4];"
    :"=r"(r[0]),"=r"(r[1]),"=r"(r[2]),"=r"(r[3]):"r"(a));
}
// fp16 MMA, fp32 accumulate
__device__ __forceinline__ void mmah(float* d, const uint32_t* a, uint32_t b0, uint32_t b1){
  asm volatile("mma.sync.aligned.m16n8k16.row.col.f32.f16.f16.f32 "
    "{%0,%1,%2,%3},{%4,%5,%6,%7},{%8,%9},{%0,%1,%2,%3};"
    :"+f"(d[0]),"+f"(d[1]),"+f"(d[2]),"+f"(d[3])
    :"r"(a[0]),"r"(a[1]),"r"(a[2]),"r"(a[3]),"r"(b0),"r"(b1));
}
__device__ __forceinline__ uint32_t packh(float a, float b){
  __half2 h=__floats2half2_rn(a,b);
  return *(uint32_t*)&h;
}
__device__ __forceinline__ float ex2(float x){
  float r; asm("ex2.approx.ftz.f32 %0,%1;":"=f"(r):"f"(x)); return r;
}
__device__ __forceinline__ uint32_t h2ex2(uint32_t x){
  uint32_t r; asm("ex2.approx.f16x2 %0,%1;":"=r"(r):"r"(x)); return r;
}
__device__ __forceinline__ uint32_t h2sub(uint32_t a, uint32_t b){
  uint32_t r; asm("sub.rn.f16x2 %0,%1,%2;":"=r"(r):"r"(a),"r"(b)); return r;
}
// gelu(x) = x * (1 - 1/(exp(2z)+1)), z = 0.79788456(x + 0.044715 x^3)
__device__ __forceinline__ float gelu_fast(float x){
  const float z = 0.7978845608028654f*(x + 0.044715f*x*x*x);
  const float e = ex2(z*2.8853900817779268f);   // exp(2z)
  float r; asm("rcp.approx.ftz.f32 %0,%1;":"=f"(r):"f"(e+1.0f));
  return x - x*r;
}
__device__ __forceinline__ uint32_t soff(uint32_t r, uint32_t ch){
  return r*128u + ((ch ^ (r & 7u)) << 4);
}

// ---------------- elementwise ----------------
__global__ void __launch_bounds__(256) ln_half_kernel(const float* __restrict__ x,
    const float* __restrict__ sc_, const float* __restrict__ bi_,
    __half* __restrict__ oh){
  const int row=blockIdx.x, t=threadIdx.x;
  const float4 v=((const float4*)(x+(size_t)row*DIM))[t];
  float s=v.x+v.y+v.z+v.w, ss=v.x*v.x+v.y*v.y+v.z*v.z+v.w*v.w;
  #pragma unroll
  for(int o=16;o;o>>=1){ s+=__shfl_xor_sync(~0u,s,o); ss+=__shfl_xor_sync(~0u,ss,o); }
  __shared__ float sm1[8], sm2[8];
  if((t&31)==0){ sm1[t>>5]=s; sm2[t>>5]=ss; }
  __syncthreads();
  float tot=0.f,tot2=0.f;
  #pragma unroll
  for(int i=0;i<8;i++){ tot+=sm1[i]; tot2+=sm2[i]; }
  const float mean=tot*(1.f/DIM), var=tot2*(1.f/DIM)-mean*mean, inv=rsqrtf(var+1e-6f);
  const float4 sc=((const float4*)sc_)[t], bi=((const float4*)bi_)[t];
  float o0=(v.x-mean)*inv*sc.x+bi.x, o1=(v.y-mean)*inv*sc.y+bi.y;
  float o2=(v.z-mean)*inv*sc.z+bi.z, o3=(v.w-mean)*inv*sc.w+bi.w;
  ((uint2*)(oh+(size_t)row*DIM))[t]=make_uint2(packh(o0,o1),packh(o2,o3));
}

__global__ void __launch_bounds__(256) kvpe_half_kernel(const float* __restrict__ kv,
    const float* __restrict__ pe, const int* __restrict__ ids,
    __half* __restrict__ oh){
  const int row=blockIdx.x, t=threadIdx.x;
  const int id=ids[row];
  float4 a=((const float4*)(kv+(size_t)row*DIM))[t];
  const float4 p=((const float4*)(pe+(size_t)id*DIM))[t];
  a.x+=p.x; a.y+=p.y; a.z+=p.z; a.w+=p.w;
  ((uint2*)(oh+(size_t)row*DIM))[t]=make_uint2(packh(a.x,a.y),packh(a.z,a.w));
}

// W[K,N] -> Wt[N,K] single fp16, 64x64 tiles, vectorized
__global__ void __launch_bounds__(256) tconv_kernel(const float* __restrict__ W,
    __half* __restrict__ T, int K, int N){
  __shared__ float t[64][65];
  const int tid=threadIdx.x;
  const int bx=blockIdx.x*64, by=blockIdx.y*64;
  const int lr=tid>>4, lc=(tid&15)*4;
  #pragma unroll
  for(int i=0;i<4;i++){
    const int row=lr+i*16;
    const float4 v=*(const float4*)(W+(size_t)(by+row)*N+bx+lc);
    t[row][lc]=v.x; t[row][lc+1]=v.y; t[row][lc+2]=v.z; t[row][lc+3]=v.w;
  }
  __syncthreads();
  #pragma unroll
  for(int i=0;i<4;i++){
    const int n=lr+i*16;
    const uint32_t p0=packh(t[lc][n],   t[lc+1][n]);
    const uint32_t p1=packh(t[lc+2][n], t[lc+3][n]);
    *(uint2*)(T+(size_t)(bx+n)*K+by+lc)=make_uint2(p0,p1);
  }
}

// ---------------- fp16 1-pass GEMM: C = A[M,K] @ Wt[N,K]^T ----------------
// tile 128x128x64, 2-stage pipeline, 2 CTAs/SM; stage (32KB): A@0 (16KB), B@16384
#define MM1_STAGE 32768
#define MM1_SMEM  (2*MM1_STAGE)

__device__ __forceinline__ void mm1_load(const __half* A,const __half* B,
    uint32_t sb,int tid,int row0,int col0,int K,int s){
  const int k0=s*64; const uint32_t st=sb+(s&1)*MM1_STAGE;
  #pragma unroll
  for(int i=0;i<4;i++){
    int id=tid+256*i; uint32_t r=id>>3, c=id&7; uint32_t so=soff(r,c);
    cp16(st+so,       A+(size_t)(row0+r)*K+k0+c*8);
    cp16(st+16384+so, B+(size_t)(col0+r)*K+k0+c*8);
  }
}

// EPI: 0 = gelu -> fp16, 1 = +residual -> fp32, 2 = xSCALEC -> fp16, 4 = plain fp16
template <int EPI>
__global__ void __launch_bounds__(256,2) mm1_kernel(const __half* __restrict__ A,
    const __half* __restrict__ B,
    const float* __restrict__ R, float* __restrict__ Cf,
    __half* __restrict__ Ch, int N, int K){
  extern __shared__ char smc[];
  const uint32_t sb=smem_u32(smc);
  const int tid=threadIdx.x, wid=tid>>5, lane=tid&31;
  const int row0=blockIdx.y*128, col0=blockIdx.x*128;
  const int m0=(wid>>2)*64, n0=(wid&3)*32;

  float acc[4][4][4];
  #pragma unroll
  for(int i=0;i<4;i++)
    #pragma unroll
    for(int j=0;j<4;j++)
      #pragma unroll
      for(int k=0;k<4;k++) acc[i][j][k]=0.f;

  const int S=K/64;
  mm1_load(A,B,sb,tid,row0,col0,K,0); CP_COMMIT();
  mm1_load(A,B,sb,tid,row0,col0,K,1); CP_COMMIT();

  for(int s=0;s<S;s++){
    CP_WAIT1();
    __syncthreads();
    const uint32_t st=sb+(s&1)*MM1_STAGE;
    #pragma unroll
    for(int kk=0;kk<4;kk++){
      const uint32_t chk=kk*2+(lane>>4);
      uint32_t bh[2][4];
      #pragma unroll
      for(int ni=0;ni<2;ni++){
        const uint32_t r=n0+ni*16+(lane&15);
        ldsm4(bh[ni], st+16384+soff(r,chk));
      }
      #pragma unroll
      for(int mi=0;mi<4;mi++){
        const uint32_t r=m0+mi*16+(lane&15);
        uint32_t a[4];
        ldsm4(a, st+soff(r,chk));
        #pragma unroll
        for(int nj=0;nj<4;nj++)
          mmah(acc[mi][nj], a, bh[nj>>1][nj&1], bh[nj>>1][(nj&1)+2]);
      }
    }
    __syncthreads();
    if(s+2<S) mm1_load(A,B,sb,tid,row0,col0,K,s+2);
    CP_COMMIT();
  }

  #pragma unroll
  for(int mi=0;mi<4;mi++){
    #pragma unroll
    for(int h=0;h<2;h++){
      const int grow=row0+m0+mi*16+(lane>>2)+h*8;
      #pragma unroll
      for(int nj=0;nj<4;nj++){
        const int gcol=col0+n0+nj*8+2*(lane&3);
        const float v0=acc[mi][nj][2*h], v1=acc[mi][nj][2*h+1];
        if(EPI==1){
          float2 rv=*(const float2*)(R+(size_t)grow*N+gcol);
          *(float2*)(Cf+(size_t)grow*N+gcol)=make_float2(v0+rv.x, v1+rv.y);
        } else if(EPI==0){
          *(uint32_t*)(Ch+(size_t)grow*N+gcol)=packh(gelu_fast(v0),gelu_fast(v1));
        } else if(EPI==2){
          *(uint32_t*)(Ch+(size_t)grow*N+gcol)=packh(v0*SCALEC,v1*SCALEC);
        } else {
          *(uint32_t*)(Ch+(size_t)grow*N+gcol)=packh(v0,v1);
        }
      }
    }
  }
}

// ---------------- FA2 attention (fp16 1-pass HMMA), 128 threads, 2 CTAs/SM ----------------
// smem: Q @0 (16KB); stage buf @16384+buf*16384: K@+0 (8KB), V@+8192 (8KB). total 48KB
// Q fragments in registers; probs computed in fp16x2 (ex2.approx.f16x2);
// row sums (l) accumulated by ones-MMA alongside PV.
#define AT_SMEM 49152
#define ONE2 0x3C003C00u

__device__ __forceinline__ void attn_loadkv(const __half* KV,
    uint32_t sb,int tid,size_t kr0,int h,int buf){
  const uint32_t st=sb+16384+buf*16384;
  #pragma unroll
  for(int i=0;i<4;i++){
    int id=tid+128*i; uint32_t r=id>>3, c=id&7; uint32_t so=soff(r,c);
    const size_t g=(kr0+r)*2048 + (size_t)h*64 + c*8;
    cp16(st+so,      KV+g);
    cp16(st+8192+so, KV+g+1024);
  }
}

__global__ void __launch_bounds__(128,2) attn_kernel(const __half* __restrict__ Q,
    const __half* __restrict__ KV, __half* __restrict__ C){
  extern __shared__ char smc[];
  const uint32_t sb=smem_u32(smc);
  const int tid=threadIdx.x, wid=tid>>5, lane=tid&31;
  const int qt=blockIdx.x, h=blockIdx.y, b=blockIdx.z;
  const size_t qrow0=(size_t)(b*QL+qt*128);

  #pragma unroll
  for(int i=0;i<8;i++){
    int id=tid+128*i; uint32_t r=id>>3, c=id&7; uint32_t so=soff(r,c);
    cp16(sb+so, Q+(qrow0+r)*DIM + (size_t)h*64 + c*8);
  }
  CP_COMMIT();
  attn_loadkv(KV,sb,tid,(size_t)b*KL,h,0); CP_COMMIT();
  attn_loadkv(KV,sb,tid,(size_t)b*KL+64,h,1); CP_COMMIT();

  // preload Q fragments into registers
  uint32_t qreg[4][2][4];
  CP_WAIT2();
  __syncthreads();
  #pragma unroll
  for(int kk=0;kk<4;kk++){
    const uint32_t chk=kk*2+(lane>>4);
    #pragma unroll
    for(int mi=0;mi<2;mi++){
      const uint32_t r=wid*32+mi*16+(lane&15);
      ldsm4(qreg[kk][mi], sb+soff(r,chk));
    }
  }

  float O[2][8][4];
  float L[2][4];
  #pragma unroll
  for(int i=0;i<2;i++){
    #pragma unroll
    for(int j=0;j<8;j++)
      #pragma unroll
      for(int k=0;k<4;k++) O[i][j][k]=0.f;
    #pragma unroll
    for(int k=0;k<4;k++) L[i][k]=0.f;
  }
  float mrun[2][2]={{-1e30f,-1e30f},{-1e30f,-1e30f}};

  const int NT=KL/64;
  for(int t=0;t<NT;t++){
    if(t+1<NT) CP_WAIT1(); else CP_WAIT0();
    __syncthreads();
    const uint32_t st=sb+16384+(t&1)*16384;

    // ---- S = Q @ K^T (1-pass fp16) ----
    float S[2][8][4];
    #pragma unroll
    for(int i=0;i<2;i++)
      #pragma unroll
      for(int j=0;j<8;j++)
        #pragma unroll
        for(int k=0;k<4;k++) S[i][j][k]=0.f;
    #pragma unroll
    for(int kk=0;kk<4;kk++){
      const uint32_t chk=kk*2+(lane>>4);
      #pragma unroll
      for(int nk=0;nk<4;nk++){
        const uint32_t r=nk*16+(lane&15);
        uint32_t kh[4];
        ldsm4(kh, st+soff(r,chk));
        #pragma unroll
        for(int mi=0;mi<2;mi++){
          mmah(S[mi][2*nk],   qreg[kk][mi], kh[0], kh[2]);
          mmah(S[mi][2*nk+1], qreg[kk][mi], kh[1], kh[3]);
        }
      }
    }

    // ---- online softmax: probs in fp16x2, l via ones-MMA ----
    uint32_t P[2][16];
    #pragma unroll
    for(int mi=0;mi<2;mi++){
      #pragma unroll
      for(int hh=0;hh<2;hh++){
        float mx=-1e30f;
        #pragma unroll
        for(int nj=0;nj<8;nj++){ mx=fmaxf(mx,S[mi][nj][2*hh]); mx=fmaxf(mx,S[mi][nj][2*hh+1]); }
        mx=fmaxf(mx,__shfl_xor_sync(~0u,mx,1));
        mx=fmaxf(mx,__shfl_xor_sync(~0u,mx,2));
        // half-rounded running max (offset cancels in p/l; exact in f32)
        const float mn=fmaxf(mrun[mi][hh],mx);
        const __half mnh=__float2half_rn(mn);
        const float mnf=__half2float(mnh);
        const float alpha=ex2(mrun[mi][hh]-mnf);
        mrun[mi][hh]=mnf;
        const __half2 mn2h=__half2half2(mnh);
        const uint32_t mn2=*(const uint32_t*)&mn2h;
        #pragma unroll
        for(int nj=0;nj<8;nj++){
          uint32_t v=packh(S[mi][nj][2*hh],S[mi][nj][2*hh+1]);
          P[mi][nj*2+hh]=h2ex2(h2sub(v,mn2));
          O[mi][nj][2*hh]  *=alpha;
          O[mi][nj][2*hh+1]*=alpha;
        }
        L[mi][2*hh]  *=alpha;
        L[mi][2*hh+1]*=alpha;
      }
    }

    // ---- O += P @ V; L += P @ ones ----
    #pragma unroll
    for(int ki=0;ki<4;ki++){
      uint32_t p[2][4];
      #pragma unroll
      for(int mi=0;mi<2;mi++){
        p[mi][0]=P[mi][(2*ki)*2];
        p[mi][1]=P[mi][(2*ki)*2+1];
        p[mi][2]=P[mi][(2*ki+1)*2];
        p[mi][3]=P[mi][(2*ki+1)*2+1];
        mmah(L[mi], p[mi], ONE2, ONE2);
      }
      #pragma unroll
      for(int nd=0;nd<4;nd++){
        const uint32_t r=ki*16+(lane&15);
        const uint32_t chk=nd*2+(lane>>4);
        uint32_t vh[4];
        ldsm4t(vh, st+8192+soff(r,chk));
        #pragma unroll
        for(int mi=0;mi<2;mi++){
          mmah(O[mi][2*nd],   p[mi], vh[0], vh[1]);
          mmah(O[mi][2*nd+1], p[mi], vh[2], vh[3]);
        }
      }
    }
    __syncthreads();
    if(t+2<NT){ attn_loadkv(KV,sb,tid,(size_t)b*KL+(size_t)(t+2)*64,h,t&1); CP_COMMIT(); }
  }

  #pragma unroll
  for(int mi=0;mi<2;mi++)
    #pragma unroll
    for(int hh=0;hh<2;hh++){
      const float inv=1.f/L[mi][2*hh];
      const size_t grow=qrow0+wid*32+mi*16+(lane>>2)+hh*8;
      #pragma unroll
      for(int nj=0;nj<8;nj++){
        const int gcol=h*64+nj*8+2*(lane&3);
        *(uint32_t*)(C+grow*DIM+gcol)=packh(O[mi][nj][2*hh]*inv, O[mi][nj][2*hh+1]*inv);
      }
    }
}

// ---------------- launch ----------------
extern "C" void kernel_launch(void* const* d_in, const int* in_sizes, int n_in,
                              void* d_out, int out_size){
  const float* q   =(const float*)d_in[0];
  const float* kv  =(const float*)d_in[1];
  const int*   ids =(const int*)  d_in[3];
  const float* ln1s=(const float*)d_in[4];
  const float* ln1b=(const float*)d_in[5];
  const float* Wq  =(const float*)d_in[6];
  const float* Wkv =(const float*)d_in[7];
  const float* Wo  =(const float*)d_in[8];
  const float* ln2s=(const float*)d_in[9];
  const float* ln2b=(const float*)d_in[10];
  const float* W1  =(const float*)d_in[11];
  const float* W2  =(const float*)d_in[12];
  const float* pe  =(const float*)d_in[13];
  float* out=(float*)d_out;

#define SYM(v,s) void* v##_; cudaGetSymbolAddress(&v##_,s);
  SYM(wq,w_q) SYM(wkv,w_kv) SYM(wo,w_o) SYM(w1,w_1) SYM(w2,w_2)
  SYM(qln,g_qln) SYM(kpe,g_kvpe) SYM(qp,g_qp) SYM(kvp,g_kvp)
  SYM(ctx,g_ctx) SYM(atf,g_attn) SYM(hbuf,g_hb) SYM(inbuf,g_in)
#undef SYM
#define HF(p) ((__half*)p##_)
#define FL(p) ((float*)p##_)

  cudaFuncSetAttribute(mm1_kernel<0>, cudaFuncAttributeMaxDynamicSharedMemorySize, MM1_SMEM);
  cudaFuncSetAttribute(mm1_kernel<1>, cudaFuncAttributeMaxDynamicSharedMemorySize, MM1_SMEM);
  cudaFuncSetAttribute(mm1_kernel<2>, cudaFuncAttributeMaxDynamicSharedMemorySize, MM1_SMEM);
  cudaFuncSetAttribute(mm1_kernel<4>, cudaFuncAttributeMaxDynamicSharedMemorySize, MM1_SMEM);
  cudaFuncSetAttribute(attn_kernel,   cudaFuncAttributeMaxDynamicSharedMemorySize, AT_SMEM);

  // ncu captures launch #4 -> keep the biggest GEMM (kv-proj) there
  tconv_kernel<<<dim3(2*DIM/64,DIM/64),256>>>(Wkv, HF(wkv), DIM, 2*DIM);             // 1
  kvpe_half_kernel<<<MKV,256>>>(kv, pe, ids, HF(kpe));                               // 2
  tconv_kernel<<<dim3(DIM/64,DIM/64),256>>>(Wq, HF(wq), DIM, DIM);                   // 3
  mm1_kernel<4><<<dim3(2*DIM/128,MKV/128),256,MM1_SMEM>>>(HF(kpe),HF(wkv),
      nullptr,nullptr,HF(kvp),2*DIM,DIM);                                            // 4 (ncu)
  ln_half_kernel<<<MQ,256>>>(q, ln1s, ln1b, HF(qln));                                // 5
  mm1_kernel<2><<<dim3(DIM/128,MQ/128),256,MM1_SMEM>>>(HF(qln),HF(wq),
      nullptr,nullptr,HF(qp),DIM,DIM);                                               // 6
  tconv_kernel<<<dim3(DIM/64,DIM/64),256>>>(Wo, HF(wo), DIM, DIM);                   // 7
  tconv_kernel<<<dim3(INNER/64,DIM/64),256>>>(W1, HF(w1), DIM, INNER);               // 8
  tconv_kernel<<<dim3(DIM/64,INNER/64),256>>>(W2, HF(w2), INNER, DIM);               // 9

  attn_kernel<<<dim3(QL/128,HEADS,BATCH),128,AT_SMEM>>>(HF(qp),HF(kvp),HF(ctx));     // 10

  mm1_kernel<1><<<dim3(DIM/128,MQ/128),256,MM1_SMEM>>>(HF(ctx),HF(wo),
      q,FL(atf),nullptr,DIM,DIM);                                                    // 11
  ln_half_kernel<<<MQ,256>>>(FL(atf), ln2s, ln2b, HF(hbuf));                         // 12
  mm1_kernel<0><<<dim3(INNER/128,MQ/128),256,MM1_SMEM>>>(HF(hbuf),HF(w1),
      nullptr,nullptr,HF(inbuf),INNER,DIM);                                          // 13
  mm1_kernel<1><<<dim3(DIM/128,MQ/128),256,MM1_SMEM>>>(HF(inbuf),HF(w2),
      FL(atf),out,nullptr,DIM,INNER);                                                // 14
}

// round 17
// speedup vs baseline: 1.0695x; 1.0050x over previous
#include <cuda_runtime.h>
#include <cuda_fp16.h>
#include <cstdint>
#include <math.h>

#define DIM    1024
#define HEADS  16
#define DH     64
#define BATCH  2
#define QL     1024
#define KL     4096
#define INNER  4096
#define MQ     (BATCH*QL)
#define MKV    (BATCH*KL)

// 0.125 * log2(e): folded into Wq weights so softmax works in exp2 domain
#define SCALEC 0.18033688011112042f

// ---------------- scratch ----------------
#define ALN __align__(256)
__device__ ALN __half w_q [DIM*DIM];            // pre-scaled x SCALEC
__device__ ALN __half w_kv[2*DIM*DIM];
__device__ ALN __half w_o [DIM*DIM];
__device__ ALN __half w_1 [INNER*DIM];
__device__ ALN __half w_2 [DIM*INNER];
__device__ ALN __half g_qln [MQ*DIM];
__device__ ALN __half g_kvpe[MKV*DIM];
__device__ ALN __half g_qp  [MQ*DIM];
__device__ ALN __half g_kvp [MKV*2*DIM];        // K|V
__device__ ALN __half g_ctx [MQ*DIM];
__device__ ALN float  g_attn[MQ*DIM];
__device__ ALN __half g_hb  [MQ*DIM];
__device__ ALN __half g_in  [MQ*INNER];
__device__ ALN float  g_sp  [4*MQ*DIM];         // split-K partials

// ---------------- PTX helpers (sm_80-compatible only) ----------------
__device__ __forceinline__ uint32_t smem_u32(const void* p){ uint32_t a;
  asm("{ .reg .u64 t; cvta.to.shared.u64 t, %1; cvt.u32.u64 %0, t; }":"=r"(a):"l"(p)); return a; }
__device__ __forceinline__ void cp16(uint32_t d, const void* s){
  asm volatile("cp.async.cg.shared.global [%0],[%1],16;"::"r"(d),"l"(s)); }
#define CP_COMMIT() asm volatile("cp.async.commit_group;":::"memory")
#define CP_WAIT0()  asm volatile("cp.async.wait_group 0;":::"memory")
#define CP_WAIT1()  asm volatile("cp.async.wait_group 1;":::"memory")
#define CP_WAIT2()  asm volatile("cp.async.wait_group 2;":::"memory")

__device__ __forceinline__ void ldsm4(uint32_t* r, uint32_t a){
  asm volatile("ldmatrix.sync.aligned.m8n8.x4.shared.b16 {%0,%1,%2,%3},[%4];"
    :"=r"(r[0]),"=r"(r[1]),"=r"(r[2]),"=r"(r[3]):"r"(a));
}
__device__ __forceinline__ void ldsm4t(uint32_t* r, uint32_t a){
  asm volatile("ldmatrix.sync.aligned.m8n8.x4.trans.shared.b16 {%0,%1,%2,%3},[%4];"
    :"=r"(r[0]),"=r"(r[1]),"=r"(r[2]),"=r"(r[3]):"r"(a));
}
__device__ __forceinline__ void mmah(float* d, const uint32_t* a, uint32_t b0, uint32_t b1){
  asm volatile("mma.sync.aligned.m16n8k16.row.col.f32.f16.f16.f32 "
    "{%0,%1,%2,%3},{%4,%5,%6,%7},{%8,%9},{%0,%1,%2,%3};"
    :"+f"(d[0]),"+f"(d[1]),"+f"(d[2]),"+f"(d[3])
    :"r"(a[0]),"r"(a[1]),"r"(a[2]),"r"(a[3]),"r"(b0),"r"(b1));
}
__device__ __forceinline__ uint32_t packh(float a, float b){
  __half2 h=__floats2half2_rn(a,b);
  return *(uint32_t*)&h;
}
__device__ __forceinline__ float ex2(float x){
  float r; asm("ex2.approx.ftz.f32 %0,%1;":"=f"(r):"f"(x)); return r;
}
__device__ __forceinline__ uint32_t h2ex2(uint32_t x){
  uint32_t r; asm("ex2.approx.f16x2 %0,%1;":"=r"(r):"r"(x)); return r;
}
__device__ __forceinline__ uint32_t h2sub(uint32_t a, uint32_t b){
  uint32_t r; asm("sub.rn.f16x2 %0,%1,%2;":"=r"(r):"r"(a),"r"(b)); return r;
}
__device__ __forceinline__ float gelu_fast(float x){
  const float z = 0.7978845608028654f*(x + 0.044715f*x*x*x);
  const float e = ex2(z*2.8853900817779268f);
  float r; asm("rcp.approx.ftz.f32 %0,%1;":"=f"(r):"f"(e+1.0f));
  return x - x*r;
}
__device__ __forceinline__ uint32_t soff(uint32_t r, uint32_t ch){
  return r*128u + ((ch ^ (r & 7u)) << 4);
}

// ---------------- elementwise ----------------
__global__ void __launch_bounds__(256) ln_half_kernel(const float* __restrict__ x,
    const float* __restrict__ sc_, const float* __restrict__ bi_,
    __half* __restrict__ oh){
  const int row=blockIdx.x, t=threadIdx.x;
  const float4 v=((const float4*)(x+(size_t)row*DIM))[t];
  float s=v.x+v.y+v.z+v.w, ss=v.x*v.x+v.y*v.y+v.z*v.z+v.w*v.w;
  #pragma unroll
  for(int o=16;o;o>>=1){ s+=__shfl_xor_sync(~0u,s,o); ss+=__shfl_xor_sync(~0u,ss,o); }
  __shared__ float sm1[8], sm2[8];
  if((t&31)==0){ sm1[t>>5]=s; sm2[t>>5]=ss; }
  __syncthreads();
  float tot=0.f,tot2=0.f;
  #pragma unroll
  for(int i=0;i<8;i++){ tot+=sm1[i]; tot2+=sm2[i]; }
  const float mean=tot*(1.f/DIM), var=tot2*(1.f/DIM)-mean*mean, inv=rsqrtf(var+1e-6f);
  const float4 sc=((const float4*)sc_)[t], bi=((const float4*)bi_)[t];
  float o0=(v.x-mean)*inv*sc.x+bi.x, o1=(v.y-mean)*inv*sc.y+bi.y;
  float o2=(v.z-mean)*inv*sc.z+bi.z, o3=(v.w-mean)*inv*sc.w+bi.w;
  ((uint2*)(oh+(size_t)row*DIM))[t]=make_uint2(packh(o0,o1),packh(o2,o3));
}

__global__ void __launch_bounds__(256) kvpe_half_kernel(const float* __restrict__ kv,
    const float* __restrict__ pe, const int* __restrict__ ids,
    __half* __restrict__ oh){
  const int row=blockIdx.x, t=threadIdx.x;
  const int id=ids[row];
  float4 a=((const float4*)(kv+(size_t)row*DIM))[t];
  const float4 p=((const float4*)(pe+(size_t)id*DIM))[t];
  a.x+=p.x; a.y+=p.y; a.z+=p.z; a.w+=p.w;
  ((uint2*)(oh+(size_t)row*DIM))[t]=make_uint2(packh(a.x,a.y),packh(a.z,a.w));
}

// W[K,N] -> Wt[N,K] single fp16 (x scale), 64x64 tiles, vectorized
__global__ void __launch_bounds__(256) tconv_kernel(const float* __restrict__ W,
    __half* __restrict__ T, int K, int N, float scale){
  __shared__ float t[64][65];
  const int tid=threadIdx.x;
  const int bx=blockIdx.x*64, by=blockIdx.y*64;
  const int lr=tid>>4, lc=(tid&15)*4;
  #pragma unroll
  for(int i=0;i<4;i++){
    const int row=lr+i*16;
    const float4 v=*(const float4*)(W+(size_t)(by+row)*N+bx+lc);
    t[row][lc]=v.x*scale; t[row][lc+1]=v.y*scale; t[row][lc+2]=v.z*scale; t[row][lc+3]=v.w*scale;
  }
  __syncthreads();
  #pragma unroll
  for(int i=0;i<4;i++){
    const int n=lr+i*16;
    const uint32_t p0=packh(t[lc][n],   t[lc+1][n]);
    const uint32_t p1=packh(t[lc+2][n], t[lc+3][n]);
    *(uint2*)(T+(size_t)(bx+n)*K+by+lc)=make_uint2(p0,p1);
  }
}

// ---------------- fp16 1-pass GEMM core ----------------
// tile 128x128x64, 2-stage pipeline, 2 CTAs/SM; stage (32KB): A@0 (16KB), B@16384
#define MM1_STAGE 32768
#define MM1_SMEM  (2*MM1_STAGE)

__device__ __forceinline__ void mm1_load(const __half* A,const __half* B,
    uint32_t sb,int tid,int row0,int col0,int K,int kbase,int s){
  const int k0=kbase+s*64; const uint32_t st=sb+(s&1)*MM1_STAGE;
  #pragma unroll
  for(int i=0;i<4;i++){
    int id=tid+256*i; uint32_t r=id>>3, c=id&7; uint32_t so=soff(r,c);
    cp16(st+so,       A+(size_t)(row0+r)*K+k0+c*8);
    cp16(st+16384+so, B+(size_t)(col0+r)*K+k0+c*8);
  }
}

// core mainloop: accumulates into acc[4][4][4]; S iterations from kbase
__device__ __forceinline__ void mm1_main(const __half* A,const __half* B,
    uint32_t sb,int tid,int wid,int lane,int row0,int col0,int K,int kbase,int S,
    float acc[4][4][4]){
  const int m0=(wid>>2)*64, n0=(wid&3)*32;
  mm1_load(A,B,sb,tid,row0,col0,K,kbase,0); CP_COMMIT();
  mm1_load(A,B,sb,tid,row0,col0,K,kbase,1); CP_COMMIT();
  for(int s=0;s<S;s++){
    CP_WAIT1();
    __syncthreads();
    const uint32_t st=sb+(s&1)*MM1_STAGE;
    #pragma unroll
    for(int kk=0;kk<4;kk++){
      const uint32_t chk=kk*2+(lane>>4);
      uint32_t bh[2][4];
      #pragma unroll
      for(int ni=0;ni<2;ni++){
        const uint32_t r=n0+ni*16+(lane&15);
        ldsm4(bh[ni], st+16384+soff(r,chk));
      }
      #pragma unroll
      for(int mi=0;mi<4;mi++){
        const uint32_t r=m0+mi*16+(lane&15);
        uint32_t a[4];
        ldsm4(a, st+soff(r,chk));
        #pragma unroll
        for(int nj=0;nj<4;nj++)
          mmah(acc[mi][nj], a, bh[nj>>1][nj&1], bh[nj>>1][(nj&1)+2]);
      }
    }
    __syncthreads();
    if(s+2<S) mm1_load(A,B,sb,tid,row0,col0,K,kbase,s+2);
    CP_COMMIT();
  }
}

// EPI: 0 = gelu -> fp16, 1 = +residual -> fp32, 4 = plain fp16
template <int EPI>
__global__ void __launch_bounds__(256,2) mm1_kernel(const __half* __restrict__ A,
    const __half* __restrict__ B,
    const float* __restrict__ R, float* __restrict__ Cf,
    __half* __restrict__ Ch, int N, int K){
  extern __shared__ char smc[];
  const uint32_t sb=smem_u32(smc);
  const int tid=threadIdx.x, wid=tid>>5, lane=tid&31;
  const int row0=blockIdx.y*128, col0=blockIdx.x*128;
  const int m0=(wid>>2)*64, n0=(wid&3)*32;

  float acc[4][4][4];
  #pragma unroll
  for(int i=0;i<4;i++)
    #pragma unroll
    for(int j=0;j<4;j++)
      #pragma unroll
      for(int k=0;k<4;k++) acc[i][j][k]=0.f;

  mm1_main(A,B,sb,tid,wid,lane,row0,col0,K,0,K/64,acc);

  #pragma unroll
  for(int mi=0;mi<4;mi++){
    #pragma unroll
    for(int h=0;h<2;h++){
      const int grow=row0+m0+mi*16+(lane>>2)+h*8;
      #pragma unroll
      for(int nj=0;nj<4;nj++){
        const int gcol=col0+n0+nj*8+2*(lane&3);
        const float v0=acc[mi][nj][2*h], v1=acc[mi][nj][2*h+1];
        if(EPI==1){
          float2 rv=*(const float2*)(R+(size_t)grow*N+gcol);
          *(float2*)(Cf+(size_t)grow*N+gcol)=make_float2(v0+rv.x, v1+rv.y);
        } else if(EPI==0){
          *(uint32_t*)(Ch+(size_t)grow*N+gcol)=packh(gelu_fast(v0),gelu_fast(v1));
        } else {
          *(uint32_t*)(Ch+(size_t)grow*N+gcol)=packh(v0,v1);
        }
      }
    }
  }
}

// fused kv-proj (1024 CTAs) + q-proj (128 CTAs); both K=1024, plain fp16 out
__global__ void __launch_bounds__(256,2) mm_dual_kernel(
    const __half* __restrict__ A0, const __half* __restrict__ B0, __half* __restrict__ C0,
    const __half* __restrict__ A1, const __half* __restrict__ B1, __half* __restrict__ C1){
  extern __shared__ char smc[];
  const uint32_t sb=smem_u32(smc);
  const int tid=threadIdx.x, wid=tid>>5, lane=tid&31;
  int id=blockIdx.x;
  const __half *A,*B; __half* Ch; int N,row0,col0;
  if(id<1024){ A=A0; B=B0; Ch=C0; N=2*DIM; col0=(id&15)*128; row0=(id>>4)*128; }
  else       { id-=1024; A=A1; B=B1; Ch=C1; N=DIM; col0=(id&7)*128; row0=(id>>3)*128; }
  const int m0=(wid>>2)*64, n0=(wid&3)*32;

  float acc[4][4][4];
  #pragma unroll
  for(int i=0;i<4;i++)
    #pragma unroll
    for(int j=0;j<4;j++)
      #pragma unroll
      for(int k=0;k<4;k++) acc[i][j][k]=0.f;

  mm1_main(A,B,sb,tid,wid,lane,row0,col0,DIM,0,DIM/64,acc);

  #pragma unroll
  for(int mi=0;mi<4;mi++){
    #pragma unroll
    for(int h=0;h<2;h++){
      const int grow=row0+m0+mi*16+(lane>>2)+h*8;
      #pragma unroll
      for(int nj=0;nj<4;nj++){
        const int gcol=col0+n0+nj*8+2*(lane&3);
        *(uint32_t*)(Ch+(size_t)grow*N+gcol)=packh(acc[mi][nj][2*h],acc[mi][nj][2*h+1]);
      }
    }
  }
}

// split-K=4 GEMM for W2: partials fp32 to SP[z]
__global__ void __launch_bounds__(256,2) mm_sk_kernel(const __half* __restrict__ A,
    const __half* __restrict__ B, float* __restrict__ SP, int N, int K){
  extern __shared__ char smc[];
  const uint32_t sb=smem_u32(smc);
  const int tid=threadIdx.x, wid=tid>>5, lane=tid&31;
  const int row0=blockIdx.y*128, col0=blockIdx.x*128, z=blockIdx.z;
  const int m0=(wid>>2)*64, n0=(wid&3)*32;

  float acc[4][4][4];
  #pragma unroll
  for(int i=0;i<4;i++)
    #pragma unroll
    for(int j=0;j<4;j++)
      #pragma unroll
      for(int k=0;k<4;k++) acc[i][j][k]=0.f;

  mm1_main(A,B,sb,tid,wid,lane,row0,col0,K,z*(K/4),(K/4)/64,acc);

  float* sp=SP+(size_t)z*MQ*DIM;
  #pragma unroll
  for(int mi=0;mi<4;mi++){
    #pragma unroll
    for(int h=0;h<2;h++){
      const int grow=row0+m0+mi*16+(lane>>2)+h*8;
      #pragma unroll
      for(int nj=0;nj<4;nj++){
        const int gcol=col0+n0+nj*8+2*(lane&3);
        *(float2*)(sp+(size_t)grow*N+gcol)=make_float2(acc[mi][nj][2*h],acc[mi][nj][2*h+1]);
      }
    }
  }
}

// out = sp0+sp1+sp2+sp3 + residual
__global__ void __launch_bounds__(256) sk_reduce_kernel(const float* __restrict__ SP,
    const float* __restrict__ R, float* __restrict__ out){
  const size_t i=(size_t)blockIdx.x*256+threadIdx.x;
  float4 a=((const float4*)SP)[i];
  float4 b=((const float4*)(SP+(size_t)MQ*DIM))[i];
  float4 c=((const float4*)(SP+(size_t)2*MQ*DIM))[i];
  float4 d=((const float4*)(SP+(size_t)3*MQ*DIM))[i];
  float4 r=((const float4*)R)[i];
  float4 o;
  o.x=a.x+b.x+c.x+d.x+r.x; o.y=a.y+b.y+c.y+d.y+r.y;
  o.z=a.z+b.z+c.z+d.z+r.z; o.w=a.w+b.w+c.w+d.w+r.w;
  ((float4*)out)[i]=o;
}

// ---------------- FA2 attention (fp16 1-pass HMMA), 128 threads, 2 CTAs/SM ----------------
#define AT_SMEM 49152
#define ONE2 0x3C003C00u

__device__ __forceinline__ void attn_loadkv(const __half* KV,
    uint32_t sb,int tid,size_t kr0,int h,int buf){
  const uint32_t st=sb+16384+buf*16384;
  #pragma unroll
  for(int i=0;i<4;i++){
    int id=tid+128*i; uint32_t r=id>>3, c=id&7; uint32_t so=soff(r,c);
    const size_t g=(kr0+r)*2048 + (size_t)h*64 + c*8;
    cp16(st+so,      KV+g);
    cp16(st+8192+so, KV+g+1024);
  }
}

__global__ void __launch_bounds__(128,2) attn_kernel(const __half* __restrict__ Q,
    const __half* __restrict__ KV, __half* __restrict__ C){
  extern __shared__ char smc[];
  const uint32_t sb=smem_u32(smc);
  const int tid=threadIdx.x, wid=tid>>5, lane=tid&31;
  const int qt=blockIdx.x, h=blockIdx.y, b=blockIdx.z;
  const size_t qrow0=(size_t)(b*QL+qt*128);

  #pragma unroll
  for(int i=0;i<8;i++){
    int id=tid+128*i; uint32_t r=id>>3, c=id&7; uint32_t so=soff(r,c);
    cp16(sb+so, Q+(qrow0+r)*DIM + (size_t)h*64 + c*8);
  }
  CP_COMMIT();
  attn_loadkv(KV,sb,tid,(size_t)b*KL,h,0); CP_COMMIT();
  attn_loadkv(KV,sb,tid,(size_t)b*KL+64,h,1); CP_COMMIT();

  uint32_t qreg[4][2][4];
  CP_WAIT2();
  __syncthreads();
  #pragma unroll
  for(int kk=0;kk<4;kk++){
    const uint32_t chk=kk*2+(lane>>4);
    #pragma unroll
    for(int mi=0;mi<2;mi++){
      const uint32_t r=wid*32+mi*16+(lane&15);
      ldsm4(qreg[kk][mi], sb+soff(r,chk));
    }
  }

  float O[2][8][4];
  float L[2][4];
  #pragma unroll
  for(int i=0;i<2;i++){
    #pragma unroll
    for(int j=0;j<8;j++)
      #pragma unroll
      for(int k=0;k<4;k++) O[i][j][k]=0.f;
    #pragma unroll
    for(int k=0;k<4;k++) L[i][k]=0.f;
  }
  float mrun[2][2]={{-1e30f,-1e30f},{-1e30f,-1e30f}};

  const int NT=KL/64;
  for(int t=0;t<NT;t++){
    if(t+1<NT) CP_WAIT1(); else CP_WAIT0();
    __syncthreads();
    const uint32_t st=sb+16384+(t&1)*16384;

    float S[2][8][4];
    #pragma unroll
    for(int i=0;i<2;i++)
      #pragma unroll
      for(int j=0;j<8;j++)
        #pragma unroll
        for(int k=0;k<4;k++) S[i][j][k]=0.f;
    #pragma unroll
    for(int kk=0;kk<4;kk++){
      const uint32_t chk=kk*2+(lane>>4);
      #pragma unroll
      for(int nk=0;nk<4;nk++){
        const uint32_t r=nk*16+(lane&15);
        uint32_t kh[4];
        ldsm4(kh, st+soff(r,chk));
        #pragma unroll
        for(int mi=0;mi<2;mi++){
          mmah(S[mi][2*nk],   qreg[kk][mi], kh[0], kh[2]);
          mmah(S[mi][2*nk+1], qreg[kk][mi], kh[1], kh[3]);
        }
      }
    }

    uint32_t P[2][16];
    #pragma unroll
    for(int mi=0;mi<2;mi++){
      #pragma unroll
      for(int hh=0;hh<2;hh++){
        float mx=-1e30f;
        #pragma unroll
        for(int nj=0;nj<8;nj++){ mx=fmaxf(mx,S[mi][nj][2*hh]); mx=fmaxf(mx,S[mi][nj][2*hh+1]); }
        mx=fmaxf(mx,__shfl_xor_sync(~0u,mx,1));
        mx=fmaxf(mx,__shfl_xor_sync(~0u,mx,2));
        const float mn=fmaxf(mrun[mi][hh],mx);
        const __half mnh=__float2half_rn(mn);
        const float mnf=__half2float(mnh);
        const float alpha=ex2(mrun[mi][hh]-mnf);
        mrun[mi][hh]=mnf;
        const __half2 mn2h=__half2half2(mnh);
        const uint32_t mn2=*(const uint32_t*)&mn2h;
        #pragma unroll
        for(int nj=0;nj<8;nj++){
          uint32_t v=packh(S[mi][nj][2*hh],S[mi][nj][2*hh+1]);
          P[mi][nj*2+hh]=h2ex2(h2sub(v,mn2));
          O[mi][nj][2*hh]  *=alpha;
          O[mi][nj][2*hh+1]*=alpha;
        }
        L[mi][2*hh]  *=alpha;
        L[mi][2*hh+1]*=alpha;
      }
    }

    #pragma unroll
    for(int ki=0;ki<4;ki++){
      uint32_t p[2][4];
      #pragma unroll
      for(int mi=0;mi<2;mi++){
        p[mi][0]=P[mi][(2*ki)*2];
        p[mi][1]=P[mi][(2*ki)*2+1];
        p[mi][2]=P[mi][(2*ki+1)*2];
        p[mi][3]=P[mi][(2*ki+1)*2+1];
        mmah(L[mi], p[mi], ONE2, ONE2);
      }
      #pragma unroll
      for(int nd=0;nd<4;nd++){
        const uint32_t r=ki*16+(lane&15);
        const uint32_t chk=nd*2+(lane>>4);
        uint32_t vh[4];
        ldsm4t(vh, st+8192+soff(r,chk));
        #pragma unroll
        for(int mi=0;mi<2;mi++){
          mmah(O[mi][2*nd],   p[mi], vh[0], vh[1]);
          mmah(O[mi][2*nd+1], p[mi], vh[2], vh[3]);
        }
      }
    }
    __syncthreads();
    if(t+2<NT){ attn_loadkv(KV,sb,tid,(size_t)b*KL+(size_t)(t+2)*64,h,t&1); CP_COMMIT(); }
  }

  #pragma unroll
  for(int mi=0;mi<2;mi++)
    #pragma unroll
    for(int hh=0;hh<2;hh++){
      const float inv=1.f/L[mi][2*hh];
      const size_t grow=qrow0+wid*32+mi*16+(lane>>2)+hh*8;
      #pragma unroll
      for(int nj=0;nj<8;nj++){
        const int gcol=h*64+nj*8+2*(lane&3);
        *(uint32_t*)(C+grow*DIM+gcol)=packh(O[mi][nj][2*hh]*inv, O[mi][nj][2*hh+1]*inv);
      }
    }
}

// ---------------- launch ----------------
extern "C" void kernel_launch(void* const* d_in, const int* in_sizes, int n_in,
                              void* d_out, int out_size){
  const float* q   =(const float*)d_in[0];
  const float* kv  =(const float*)d_in[1];
  const int*   ids =(const int*)  d_in[3];
  const float* ln1s=(const float*)d_in[4];
  const float* ln1b=(const float*)d_in[5];
  const float* Wq  =(const float*)d_in[6];
  const float* Wkv =(const float*)d_in[7];
  const float* Wo  =(const float*)d_in[8];
  const float* ln2s=(const float*)d_in[9];
  const float* ln2b=(const float*)d_in[10];
  const float* W1  =(const float*)d_in[11];
  const float* W2  =(const float*)d_in[12];
  const float* pe  =(const float*)d_in[13];
  float* out=(float*)d_out;

#define SYM(v,s) void* v##_; cudaGetSymbolAddress(&v##_,s);
  SYM(wq,w_q) SYM(wkv,w_kv) SYM(wo,w_o) SYM(w1,w_1) SYM(w2,w_2)
  SYM(qln,g_qln) SYM(kpe,g_kvpe) SYM(qp,g_qp) SYM(kvp,g_kvp)
  SYM(ctx,g_ctx) SYM(atf,g_attn) SYM(hbuf,g_hb) SYM(inbuf,g_in) SYM(sp,g_sp)
#undef SYM
#define HF(p) ((__half*)p##_)
#define FL(p) ((float*)p##_)

  cudaFuncSetAttribute(mm1_kernel<0>, cudaFuncAttributeMaxDynamicSharedMemorySize, MM1_SMEM);
  cudaFuncSetAttribute(mm1_kernel<1>, cudaFuncAttributeMaxDynamicSharedMemorySize, MM1_SMEM);
  cudaFuncSetAttribute(mm_dual_kernel,cudaFuncAttributeMaxDynamicSharedMemorySize, MM1_SMEM);
  cudaFuncSetAttribute(mm_sk_kernel,  cudaFuncAttributeMaxDynamicSharedMemorySize, MM1_SMEM);
  cudaFuncSetAttribute(attn_kernel,   cudaFuncAttributeMaxDynamicSharedMemorySize, AT_SMEM);

  tconv_kernel<<<dim3(2*DIM/64,DIM/64),256>>>(Wkv, HF(wkv), DIM, 2*DIM, 1.0f);       // 1
  kvpe_half_kernel<<<MKV,256>>>(kv, pe, ids, HF(kpe));                               // 2
  tconv_kernel<<<dim3(DIM/64,DIM/64),256>>>(Wq, HF(wq), DIM, DIM, SCALEC);           // 3
  ln_half_kernel<<<MQ,256>>>(q, ln1s, ln1b, HF(qln));                                // 4
  // fused kv-proj + q-proj
  mm_dual_kernel<<<1152,256,MM1_SMEM>>>(HF(kpe),HF(wkv),HF(kvp),
                                        HF(qln),HF(wq), HF(qp));                     // 5
  tconv_kernel<<<dim3(DIM/64,DIM/64),256>>>(Wo, HF(wo), DIM, DIM, 1.0f);             // 6
  tconv_kernel<<<dim3(INNER/64,DIM/64),256>>>(W1, HF(w1), DIM, INNER, 1.0f);         // 7
  tconv_kernel<<<dim3(DIM/64,INNER/64),256>>>(W2, HF(w2), INNER, DIM, 1.0f);         // 8

  attn_kernel<<<dim3(QL/128,HEADS,BATCH),128,AT_SMEM>>>(HF(qp),HF(kvp),HF(ctx));     // 9

  mm1_kernel<1><<<dim3(DIM/128,MQ/128),256,MM1_SMEM>>>(HF(ctx),HF(wo),
      q,FL(atf),nullptr,DIM,DIM);                                                    // 10
  ln_half_kernel<<<MQ,256>>>(FL(atf), ln2s, ln2b, HF(hbuf));                         // 11
  mm1_kernel<0><<<dim3(INNER/128,MQ/128),256,MM1_SMEM>>>(HF(hbuf),HF(w1),
      nullptr,nullptr,HF(inbuf),INNER,DIM);                                          // 12
  // W2 split-K=4 + reduce(+residual)
  mm_sk_kernel<<<dim3(DIM/128,MQ/128,4),256,MM1_SMEM>>>(HF(inbuf),HF(w2),
      FL(sp),DIM,INNER);                                                             // 13
  sk_reduce_kernel<<<MQ*DIM/1024,256>>>(FL(sp), FL(atf), out);                       // 14
}